// round 10
// baseline (speedup 1.0000x reference)
#include <cuda_runtime.h>
#include <cuda_fp16.h>
#include <math.h>
#include <stdint.h>

// ---------------------------------------------------------------------------
// HypRelEncoder — round 9:
//  * aggregation FUSED into the FUSE GEMM A-fill (nin/nout buffers deleted)
//  * per-edge norm precomputed once in CSR build (enorm, x-independent)
//  * fp16 mma.m16n8k16 + ldmatrix + register-staged W (proven round 8)
// ---------------------------------------------------------------------------

#define NE    200000
#define DIM   200
#define D4    50          // DIM / 4
#define NEDGE 500000
#define NQ    400000
#define QROW  (2*NQ)      // 800000
#define NR    200
#define NB    4096
#define QP    6
#define ALPHA 0.8f
#define MSZ   (208*208)   // padded fp16 weight matrix size

#define OFF_SUB 0
#define OFF_REL (NB*DIM)
#define OFF_QO  (2*NB*DIM)
#define OFF_QR  (OFF_QO + NB*QP*DIM)
#define OFF_X   (OFF_QR + NB*QP*DIM)
#define OFF_R   (OFF_X + NE*DIM)

// ---------------- device scratch -------------------------------------------
__device__ float g_qproj[(size_t)QROW * DIM];    // 640 MB
__device__ float g_x1  [(size_t)NE * DIM];
__device__ float g_r1[NR * DIM];
__device__ float g_dinv[2 * NE];
__device__ float g_enorm[2 * NEDGE];
__device__ __align__(16) __half g_wh[(size_t)10 * MSZ];   // padded fp16 weights
__device__ int gi_ecnt[2 * NE];
__device__ int gi_estart[2 * NE];
__device__ int gi_ecur[2 * NE];
__device__ int gi_elist[2 * NEDGE];
__device__ int gi_qcnt[2 * NEDGE];
__device__ int gi_qstart[2 * NEDGE];
__device__ int gi_qcur[2 * NEDGE];
__device__ int gi_qlist[2 * NQ];
__device__ int gi_part[1024];
__device__ int gi_psc[1024];

// ---------------- small helpers --------------------------------------------
__global__ void k_zero(float* __restrict__ p, long n) {
    long i = ((long)blockIdx.x * blockDim.x + threadIdx.x) * 4;
    long st = (long)gridDim.x * blockDim.x * 4;
    float4 z = make_float4(0.f, 0.f, 0.f, 0.f);
    for (; i < n; i += st) *(float4*)(p + i) = z;
}

__global__ void k_count_e(const int* __restrict__ ei, int* __restrict__ cnt) {
    int i = blockIdx.x * blockDim.x + threadIdx.x;
    int st = gridDim.x * blockDim.x;
    for (; i < 2 * NEDGE; i += st)
        atomicAdd(&cnt[((i >= NEDGE) ? NE : 0) + ei[2 * NEDGE + i]], 1);
}
__global__ void k_fill_e(const int* __restrict__ ei, int* __restrict__ cur,
                         int* __restrict__ list) {
    int i = blockIdx.x * blockDim.x + threadIdx.x;
    int st = gridDim.x * blockDim.x;
    for (; i < 2 * NEDGE; i += st) {
        int b = ((i >= NEDGE) ? NE : 0) + ei[2 * NEDGE + i];
        int pos = atomicAdd(&cur[b], 1);
        list[pos] = (i >= NEDGE) ? i - NEDGE : i;
    }
}
__global__ void k_count_q(const int* __restrict__ qu, int* __restrict__ cnt) {
    int j = blockIdx.x * blockDim.x + threadIdx.x;
    int st = gridDim.x * blockDim.x;
    for (; j < 2 * NQ; j += st)
        atomicAdd(&cnt[((j >= NQ) ? NEDGE : 0) + qu[2 * QROW + j]], 1);
}
__global__ void k_fill_q(const int* __restrict__ qu, int* __restrict__ cur,
                         int* __restrict__ list) {
    int j = blockIdx.x * blockDim.x + threadIdx.x;
    int st = gridDim.x * blockDim.x;
    for (; j < 2 * NQ; j += st) {
        int b = ((j >= NQ) ? NEDGE : 0) + qu[2 * QROW + j];
        int pos = atomicAdd(&cur[b], 1);
        list[pos] = j;          // GLOBAL qual id
    }
}
__global__ void k_dinv(const int* __restrict__ cnt, float* __restrict__ dinv) {
    int i = blockIdx.x * blockDim.x + threadIdx.x;
    int st = gridDim.x * blockDim.x;
    for (; i < 2 * NE; i += st) {
        int d = (i >= NE) ? 1 : 0;
        int n = i - d * NE;
        int c = cnt[(1 - d) * NE + n];
        dinv[i] = (c > 0) ? rsqrtf((float)c) : 0.f;
    }
}
// per-edge symmetric norm (global edge index i; local e = i - d*NEDGE)
__global__ void k_norm(const int* __restrict__ ei, const float* __restrict__ dinv,
                       float* __restrict__ enorm) {
    int i = blockIdx.x * blockDim.x + threadIdx.x;
    int st = gridDim.x * blockDim.x;
    for (; i < 2 * NEDGE; i += st) {
        int d = (i >= NEDGE) ? 1 : 0;
        int s  = ei[i];
        int dd = ei[2 * NEDGE + i];
        enorm[i] = dinv[d * NE + s] * dinv[d * NE + dd];
    }
}

// W fp32 [200][200] -> fp16 zero-padded [208][208]
__global__ void k_convW(const float* __restrict__ W, __half* __restrict__ dst) {
    int t = blockIdx.x * blockDim.x + threadIdx.x;
    if (t >= MSZ) return;
    int k = t / 208, n = t - k * 208;
    float v = (k < DIM && n < DIM) ? W[k * DIM + n] : 0.f;
    dst[t] = __float2half_rn(v);
}

// ---------------- two-level exclusive scan ----------------------------------
__global__ void k_scan1(const int* __restrict__ in, int* __restrict__ out,
                        int* __restrict__ part, int n) {
    __shared__ int s[1024];
    int t = threadIdx.x;
    int g = blockIdx.x * 1024 + t;
    int v = (g < n) ? in[g] : 0;
    s[t] = v;
    __syncthreads();
    for (int off = 1; off < 1024; off <<= 1) {
        int u = (t >= off) ? s[t - off] : 0;
        __syncthreads();
        s[t] += u;
        __syncthreads();
    }
    if (g < n) out[g] = s[t] - v;
    if (t == 1023 && part) part[blockIdx.x] = s[1023];
}
__global__ void k_scan_add(int* __restrict__ out, const int* __restrict__ psc, int n) {
    int g = blockIdx.x * 1024 + threadIdx.x;
    if (g < n) out[g] += psc[blockIdx.x];
}

// ---------------- fp16 tensor-core GEMM (+ fused aggregation) ----------------
// C[rows,200] = compose(A)[rows,K] @ W[K,200]; K sections of 200.
// BM=64, 8 warps (4xM, 2xN). FUSE sections 0/1 aggregate CSR edges in-kernel.

enum { M_QUAL = 0, M_FUSE = 1, M_PLAIN = 2 };

#define BM  64
#define AST 216       // half stride (432B = 27*16)
#define WST 216

__device__ __forceinline__ uint32_t s2u(const void* p) {
    return (uint32_t)__cvta_generic_to_shared(p);
}
__device__ __forceinline__ void mma16(float* c, uint32_t a0, uint32_t a1,
                                      uint32_t a2, uint32_t a3,
                                      uint32_t b0, uint32_t b1) {
    asm volatile(
        "mma.sync.aligned.m16n8k16.row.col.f32.f16.f16.f32 "
        "{%0,%1,%2,%3},{%4,%5,%6,%7},{%8,%9},{%0,%1,%2,%3};"
        : "+f"(c[0]), "+f"(c[1]), "+f"(c[2]), "+f"(c[3])
        : "r"(a0), "r"(a1), "r"(a2), "r"(a3), "r"(b0), "r"(b1));
}

template <int MODE>
__global__ void __launch_bounds__(256, 2)
k_gemm(const float* __restrict__ A,      // QUAL: x table | PLAIN: rows
       const float* __restrict__ C3,     // FUSE: x (loop section source)
       const float* __restrict__ relt,   // QUAL: rel table | FUSE: loop_rel
       const int* __restrict__ qe, const int* __restrict__ qr,
       const __half* __restrict__ Wh,    // fp16 padded; FUSE: 3 consecutive
       float* __restrict__ out,
       const float* __restrict__ bias,   // FUSE
       int nrows,
       // --- FUSE aggregation inputs ---
       const float* __restrict__ xtab, const float* __restrict__ rtab,
       const float* __restrict__ enorm,
       const int* __restrict__ ei, const int* __restrict__ et,
       const int* __restrict__ e_start, const int* __restrict__ e_cnt,
       const int* __restrict__ e_list,
       const int* __restrict__ q_start, const int* __restrict__ q_cnt,
       const int* __restrict__ q_list,
       const float* __restrict__ qproj)
{
    __shared__ __align__(16) __half As[BM * AST];
    __shared__ __align__(16) __half Wb[16 * WST];
    const int tid = threadIdx.x;
    const int wid = tid >> 5, lane = tid & 31;
    const int wm = wid >> 1, wn = wid & 1;
    const int r4 = lane >> 2, kq = lane & 3;
    const int row0 = blockIdx.x * BM;
    const int NSEC = (MODE == M_FUSE) ? 3 : 1;
    // W chunk = 16 rows x 208 halfs = 416 contiguous uint4.
    const int k0a = tid / 26, sg0 = tid - k0a * 26;
    const int s1 = tid + 256;
    const int k1a = s1 / 26, sg1 = s1 - k1a * 26;
    const bool h2nd = (tid < 160);

    float acc[13][4];
#pragma unroll
    for (int f = 0; f < 13; f++)
        acc[f][0] = acc[f][1] = acc[f][2] = acc[f][3] = 0.f;

    for (int sec = 0; sec < NSEC; sec++) {
        __syncthreads();   // prev section's MMA reads of As complete

        if (MODE == M_FUSE && sec < 2) {
            // ---- fused CSR aggregation fill: As[rr] = agg(node row0+rr, dir sec)
            const int d = sec;
            const int* srcb = ei + (size_t)d * NEDGE;
            const int* etb  = et + (size_t)d * NEDGE;
            const int* qsb  = q_start + (size_t)d * NEDGE;
            const int* qcb  = q_cnt + (size_t)d * NEDGE;
            const float* nrm = enorm + (size_t)d * NEDGE;
            const int c0 = lane, c1 = lane + 32;
            const bool has1 = (c1 < D4);
            for (int rr = wid; rr < BM; rr += 8) {
                int gr = row0 + rr;
                float4 a0 = make_float4(0.f, 0.f, 0.f, 0.f);
                float4 a1 = a0;
                if (gr < nrows) {
                    int w = d * NE + gr;
                    int beg = e_start[w], cnt = e_cnt[w];
                    for (int idx = beg; idx < beg + cnt; idx++) {
                        int e = e_list[idx];
                        float nm = nrm[e];
                        if (nm == 0.f) continue;
                        int s = srcb[e], ty = etb[e];
                        const float4* xr = (const float4*)(xtab + (size_t)s * DIM);
                        const float4* rl = (const float4*)(rtab + (size_t)ty * DIM);
                        float4 q0 = make_float4(0.f, 0.f, 0.f, 0.f);
                        float4 q1 = q0;
                        int qb = qsb[e], qc = qcb[e];
                        for (int t = qb; t < qb + qc; t++) {
                            const float4* qp =
                                (const float4*)(qproj + (size_t)q_list[t] * DIM);
                            float4 v0 = qp[c0];
                            q0.x += v0.x; q0.y += v0.y; q0.z += v0.z; q0.w += v0.w;
                            if (has1) {
                                float4 v1 = qp[c1];
                                q1.x += v1.x; q1.y += v1.y; q1.z += v1.z; q1.w += v1.w;
                            }
                        }
                        float4 xv = xr[c0], rv = rl[c0];
                        a0.x += nm * xv.x * (ALPHA * rv.x + (1.f - ALPHA) * q0.x);
                        a0.y += nm * xv.y * (ALPHA * rv.y + (1.f - ALPHA) * q0.y);
                        a0.z += nm * xv.z * (ALPHA * rv.z + (1.f - ALPHA) * q0.z);
                        a0.w += nm * xv.w * (ALPHA * rv.w + (1.f - ALPHA) * q0.w);
                        if (has1) {
                            float4 xw = xr[c1], rw = rl[c1];
                            a1.x += nm * xw.x * (ALPHA * rw.x + (1.f - ALPHA) * q1.x);
                            a1.y += nm * xw.y * (ALPHA * rw.y + (1.f - ALPHA) * q1.y);
                            a1.z += nm * xw.z * (ALPHA * rw.z + (1.f - ALPHA) * q1.z);
                            a1.w += nm * xw.w * (ALPHA * rw.w + (1.f - ALPHA) * q1.w);
                        }
                    }
                }
                // store fp16 row: lane covers float4 slots c0 and c1 (pad to 54)
                union { uint2 u; __half2 h2[2]; } p0;
                p0.h2[0] = __floats2half2_rn(a0.x, a0.y);
                p0.h2[1] = __floats2half2_rn(a0.z, a0.w);
                *reinterpret_cast<uint2*>(&As[rr * AST + c0 * 4]) = p0.u;
                if (c1 < 54) {
                    float4 v = has1 ? a1 : make_float4(0.f, 0.f, 0.f, 0.f);
                    union { uint2 u; __half2 h2[2]; } p1;
                    p1.h2[0] = __floats2half2_rn(v.x, v.y);
                    p1.h2[1] = __floats2half2_rn(v.z, v.w);
                    *reinterpret_cast<uint2*>(&As[rr * AST + c1 * 4]) = p1.u;
                }
            }
        } else {
            // ---- generic fill (QUAL / PLAIN / FUSE loop-section) ----
            for (int rr = wid; rr < BM; rr += 8) {
                int gr = row0 + rr;
                const float4 *p1 = 0, *p2 = 0;
                bool valid = gr < nrows;
                if (valid) {
                    if (MODE == M_QUAL) {
                        p1 = (const float4*)(A + (size_t)qe[gr] * DIM);
                        p2 = (const float4*)(relt + (size_t)qr[gr] * DIM);
                    } else if (MODE == M_FUSE) {   // sec == 2: loop section
                        p1 = (const float4*)(C3 + (size_t)gr * DIM);
                        p2 = (const float4*)relt;
                    } else {
                        p1 = (const float4*)(A + (size_t)gr * DIM);
                    }
                }
#pragma unroll
                for (int h = 0; h < 2; h++) {
                    int k4 = lane + 32 * h;
                    if (k4 >= 54) continue;          // 54*4 = 216 = AST
                    float4 v = make_float4(0.f, 0.f, 0.f, 0.f);
                    if (valid && k4 < D4) {
                        v = p1[k4];
                        if (MODE == M_QUAL || MODE == M_FUSE) {
                            float4 r = p2[k4];
                            v.x *= r.x; v.y *= r.y; v.z *= r.z; v.w *= r.w;
                        }
                    }
                    union { uint2 u; __half2 h2[2]; } pk;
                    pk.h2[0] = __floats2half2_rn(v.x, v.y);
                    pk.h2[1] = __floats2half2_rn(v.z, v.w);
                    *reinterpret_cast<uint2*>(&As[rr * AST + k4 * 4]) = pk.u;
                }
            }
        }

        const __half* Wg = Wh + (size_t)sec * MSZ;
        // preload W chunk 0 into registers (L2-resident)
        uint4 w0 = ((const uint4*)Wg)[tid];
        uint4 w1 = h2nd ? ((const uint4*)Wg)[s1] : make_uint4(0, 0, 0, 0);

        for (int ks = 0; ks < 13; ks++) {
            __syncthreads();        // prior chunk's ldmatrix reads of Wb done
            *(uint4*)&Wb[k0a * WST + sg0 * 8] = w0;
            if (h2nd) *(uint4*)&Wb[k1a * WST + sg1 * 8] = w1;
            if (ks < 12) {          // next-chunk LDG overlaps MMA below
                const uint4* src = (const uint4*)(Wg + (size_t)(ks + 1) * 16 * 208);
                w0 = src[tid];
                if (h2nd) w1 = src[s1];
            }
            __syncthreads();        // Wb (and As on ks==0) visible

            uint32_t a0, a1, a2, a3;
            uint32_t aaddr = s2u(&As[(wm * 16 + (lane & 15)) * AST
                                     + ks * 16 + ((lane >> 4) << 3)]);
            asm volatile("ldmatrix.sync.aligned.m8n8.x4.shared.b16 {%0,%1,%2,%3}, [%4];"
                         : "=r"(a0), "=r"(a1), "=r"(a2), "=r"(a3) : "r"(aaddr));
            int brow = ((lane >> 3) & 1) * 8 + (lane & 7);
#pragma unroll
            for (int fp = 0; fp < 6; fp++) {
                int n0 = wn * 104 + fp * 16;
                uint32_t b0, b1, b2, b3;
                uint32_t baddr = s2u(&Wb[brow * WST + n0 + ((lane >> 4) << 3)]);
                asm volatile("ldmatrix.sync.aligned.m8n8.x4.trans.shared.b16 "
                             "{%0,%1,%2,%3}, [%4];"
                             : "=r"(b0), "=r"(b1), "=r"(b2), "=r"(b3) : "r"(baddr));
                mma16(acc[2 * fp], a0, a1, a2, a3, b0, b1);
                mma16(acc[2 * fp + 1], a0, a1, a2, a3, b2, b3);
            }
            {
                int n0 = wn * 104 + 96;
                uint32_t b0, b1;
                uint32_t baddr = s2u(&Wb[brow * WST + n0]);
                asm volatile("ldmatrix.sync.aligned.m8n8.x2.trans.shared.b16 "
                             "{%0,%1}, [%2];"
                             : "=r"(b0), "=r"(b1) : "r"(baddr));
                mma16(acc[12], a0, a1, a2, a3, b0, b1);
            }
        }
    }

    // ---- epilogue ----
    int gr0 = row0 + wm * 16 + r4;
#pragma unroll
    for (int f = 0; f < 13; f++) {
        int col = wn * 104 + 8 * f + 2 * kq;
        if (col >= DIM) continue;
#pragma unroll
        for (int half = 0; half < 2; half++) {
            int gr = gr0 + 8 * half;
            if (gr >= nrows) continue;
            size_t o = (size_t)gr * DIM + col;
            float v0 = acc[f][2 * half], v1 = acc[f][2 * half + 1];
            if (MODE == M_FUSE) {
                out[o]     = tanhf(v0 * (1.f / 3.f) + bias[col]);
                out[o + 1] = tanhf(v1 * (1.f / 3.f) + bias[col + 1]);
            } else {
                out[o] = v0; out[o + 1] = v1;
            }
        }
    }
}

// ---------------- final batched gathers --------------------------------------
__global__ void k_gather(const float* __restrict__ xf, const float* __restrict__ rf,
                         const int* __restrict__ ent_ix, const int* __restrict__ rel_ix,
                         const int* __restrict__ quals_ix, float* __restrict__ out)
{
    int warp = (blockIdx.x * blockDim.x + threadIdx.x) >> 5;
    int lane = threadIdx.x & 31;
    int nwarp = (gridDim.x * blockDim.x) >> 5;
    const int total = NB * 14;
    for (int r = warp; r < total; r += nwarp) {
        int b = r / 14, s = r - b * 14;
        const float* srcp;
        float* dstp;
        if (s == 0)      { srcp = xf + (size_t)ent_ix[b] * DIM;  dstp = out + OFF_SUB + (size_t)b * DIM; }
        else if (s == 1) { srcp = rf + (size_t)rel_ix[b] * DIM;  dstp = out + OFF_REL + (size_t)b * DIM; }
        else if (s < 8)  { int p = s - 2;
                           srcp = xf + (size_t)quals_ix[b * 2 * QP + 2 * p + 1] * DIM;
                           dstp = out + OFF_QO + ((size_t)b * QP + p) * DIM; }
        else             { int p = s - 8;
                           srcp = rf + (size_t)quals_ix[b * 2 * QP + 2 * p] * DIM;
                           dstp = out + OFF_QR + ((size_t)b * QP + p) * DIM; }
        for (int c = lane; c < D4; c += 32)
            ((float4*)dstp)[c] = ((const float4*)srcp)[c];
    }
}

// ---------------------------------------------------------------------------

extern "C" void kernel_launch(void* const* d_in, const int* in_sizes, int n_in,
                              void* d_out, int out_size)
{
    const float* ent        = (const float*)d_in[0];
    const float* rel0       = (const float*)d_in[1];
    const float* w_in[2]    = {(const float*)d_in[2],  (const float*)d_in[7]};
    const float* w_out[2]   = {(const float*)d_in[3],  (const float*)d_in[8]};
    const float* w_loop[2]  = {(const float*)d_in[4],  (const float*)d_in[9]};
    const float* w_rel[2]   = {(const float*)d_in[5],  (const float*)d_in[10]};
    const float* w_q[2]     = {(const float*)d_in[6],  (const float*)d_in[11]};
    const float* loop_rel[2]= {(const float*)d_in[12], (const float*)d_in[13]};
    const float* bias[2]    = {(const float*)d_in[14], (const float*)d_in[15]};
    const int* ei       = (const int*)d_in[16];
    const int* et       = (const int*)d_in[17];
    const int* qu       = (const int*)d_in[18];
    const int* ent_ix   = (const int*)d_in[19];
    const int* rel_ix   = (const int*)d_in[20];
    const int* quals_ix = (const int*)d_in[21];
    float* out = (float*)d_out;

    float *qproj, *x1, *r1, *dinv, *enorm;
    __half* wh;
    int *ecnt, *estart, *ecur, *elist, *qcnt, *qstart, *qcur, *qlist, *part, *psc;
    cudaGetSymbolAddress((void**)&qproj,  g_qproj);
    cudaGetSymbolAddress((void**)&x1,     g_x1);
    cudaGetSymbolAddress((void**)&r1,     g_r1);
    cudaGetSymbolAddress((void**)&dinv,   g_dinv);
    cudaGetSymbolAddress((void**)&enorm,  g_enorm);
    cudaGetSymbolAddress((void**)&wh,     g_wh);
    cudaGetSymbolAddress((void**)&ecnt,   gi_ecnt);
    cudaGetSymbolAddress((void**)&estart, gi_estart);
    cudaGetSymbolAddress((void**)&ecur,   gi_ecur);
    cudaGetSymbolAddress((void**)&elist,  gi_elist);
    cudaGetSymbolAddress((void**)&qcnt,   gi_qcnt);
    cudaGetSymbolAddress((void**)&qstart, gi_qstart);
    cudaGetSymbolAddress((void**)&qcur,   gi_qcur);
    cudaGetSymbolAddress((void**)&qlist,  gi_qlist);
    cudaGetSymbolAddress((void**)&part,   gi_part);
    cudaGetSymbolAddress((void**)&psc,    gi_psc);

    // ---- fp16 weight conversion: per layer {w_in,w_out,w_loop,w_q,w_rel}
    int cb = (MSZ + 255) / 256;
    for (int L = 0; L < 2; L++) {
        k_convW<<<cb, 256>>>(w_in[L],   wh + (size_t)(L * 5 + 0) * MSZ);
        k_convW<<<cb, 256>>>(w_out[L],  wh + (size_t)(L * 5 + 1) * MSZ);
        k_convW<<<cb, 256>>>(w_loop[L], wh + (size_t)(L * 5 + 2) * MSZ);
        k_convW<<<cb, 256>>>(w_q[L],    wh + (size_t)(L * 5 + 3) * MSZ);
        k_convW<<<cb, 256>>>(w_rel[L],  wh + (size_t)(L * 5 + 4) * MSZ);
    }

    // ---- CSR build ----
    k_zero<<<256, 256>>>((float*)ecnt, 2L * NE);
    k_zero<<<512, 256>>>((float*)qcnt, 2L * NEDGE);
    k_count_e<<<2048, 256>>>(ei, ecnt);
    k_count_q<<<2048, 256>>>(qu, qcnt);

    int nbE = (2 * NE + 1023) / 1024;
    k_scan1<<<nbE, 1024>>>(ecnt, estart, part, 2 * NE);
    k_scan1<<<1, 1024>>>(part, psc, (int*)0, nbE);
    k_scan_add<<<nbE, 1024>>>(estart, psc, 2 * NE);
    cudaMemcpyAsync(ecur, estart, 2L * NE * sizeof(int), cudaMemcpyDeviceToDevice, 0);
    k_fill_e<<<2048, 256>>>(ei, ecur, elist);

    int nbQ = (2 * NEDGE + 1023) / 1024;
    k_scan1<<<nbQ, 1024>>>(qcnt, qstart, part, 2 * NEDGE);
    k_scan1<<<1, 1024>>>(part, psc, (int*)0, nbQ);
    k_scan_add<<<nbQ, 1024>>>(qstart, psc, 2 * NEDGE);
    cudaMemcpyAsync(qcur, qstart, 2L * NEDGE * sizeof(int), cudaMemcpyDeviceToDevice, 0);
    k_fill_q<<<2048, 256>>>(qu, qcur, qlist);

    k_dinv<<<512, 256>>>(ecnt, dinv);
    k_norm<<<2048, 256>>>(ei, dinv, enorm);

    float* xf = out + OFF_X;
    float* rf = out + OFF_R;

    for (int L = 0; L < 2; L++) {
        const float* xin = L ? (const float*)x1 : ent;
        const float* rin = L ? (const float*)r1 : rel0;
        float* xout = L ? xf : x1;
        float* rout = L ? rf : r1;

        // qproj[j] = (x[q_e[j]] ⊙ rel[q_r[j]]) @ w_q   (800k rows)
        k_gemm<M_QUAL><<<(QROW + BM - 1) / BM, 256>>>(
            xin, 0, rin, qu + QROW, qu,
            wh + (size_t)(L * 5 + 3) * MSZ, qproj, 0, QROW,
            0, 0, 0, 0, 0, 0, 0, 0, 0, 0, 0, 0);

        // x_out = tanh(([agg_in|agg_out|x⊙loop] @ [w_in;w_out;w_loop])/3 + b)
        // sections 0/1 aggregated in-kernel from CSR
        k_gemm<M_FUSE><<<(NE + BM - 1) / BM, 256>>>(
            0, xin, loop_rel[L], 0, 0,
            wh + (size_t)(L * 5 + 0) * MSZ, xout, bias[L], NE,
            xin, rin, enorm, ei, et,
            estart, ecnt, elist, qstart, qcnt, qlist, qproj);

        // r_out = r_in @ w_rel
        k_gemm<M_PLAIN><<<(NR + BM - 1) / BM, 256>>>(
            rin, 0, 0, 0, 0,
            wh + (size_t)(L * 5 + 4) * MSZ, rout, 0, NR,
            0, 0, 0, 0, 0, 0, 0, 0, 0, 0, 0, 0);
    }

    k_gather<<<7168, 256>>>(xf, rf, ent_ix, rel_ix, quals_ix, out);
}

// round 11
// speedup vs baseline: 1.1991x; 1.1991x over previous
#include <cuda_runtime.h>
#include <cuda_fp16.h>
#include <math.h>
#include <stdint.h>

// ---------------------------------------------------------------------------
// HypRelEncoder — round 10 (revert r9 fusion; optimize k_agg + GEMM syncs):
//  * separate k_agg restored (400k-warp parallelism was load-bearing)
//  * CSR edge RECORDS (src,ty,norm,qstart,qcnt) stored in sorted order
//  * qproj rows written in CSR-sorted order (contiguous qual ranges)
//  * GEMM: double-buffered W -> 1 sync per k-chunk
// ---------------------------------------------------------------------------

#define NE    200000
#define DIM   200
#define D4    50          // DIM / 4
#define NEDGE 500000
#define NQ    400000
#define QROW  (2*NQ)      // 800000
#define NR    200
#define NB    4096
#define QP    6
#define ALPHA 0.8f
#define MSZ   (208*208)   // padded fp16 weight matrix size

#define OFF_SUB 0
#define OFF_REL (NB*DIM)
#define OFF_QO  (2*NB*DIM)
#define OFF_QR  (OFF_QO + NB*QP*DIM)
#define OFF_X   (OFF_QR + NB*QP*DIM)
#define OFF_R   (OFF_X + NE*DIM)

// ---------------- device scratch -------------------------------------------
__device__ float g_qproj[(size_t)QROW * DIM];    // 640 MB, CSR-sorted order
__device__ float g_nin [(size_t)NE * DIM];
__device__ float g_nout[(size_t)NE * DIM];
__device__ float g_x1  [(size_t)NE * DIM];
__device__ float g_r1[NR * DIM];
__device__ float g_dinv[2 * NE];
__device__ __align__(16) __half g_wh[(size_t)10 * MSZ];   // padded fp16 weights
__device__ int   gi_ecnt[2 * NE];
__device__ int   gi_estart[2 * NE];
__device__ int   gi_ecur[2 * NE];
__device__ int   gi_qcnt[2 * NEDGE];
__device__ int   gi_qstart[2 * NEDGE];
__device__ int   gi_qcur[2 * NEDGE];
__device__ int   gi_qpos[2 * NQ];                // qual j -> sorted position
__device__ int   gi_esrc[2 * NEDGE];             // edge records (sorted order)
__device__ int   gi_ety [2 * NEDGE];
__device__ float g_enm  [2 * NEDGE];
__device__ int   gi_eqs [2 * NEDGE];
__device__ int   gi_eqc [2 * NEDGE];
__device__ int   gi_part[1024];
__device__ int   gi_psc[1024];

// ---------------- small helpers --------------------------------------------
__global__ void k_zero(float* __restrict__ p, long n) {
    long i = ((long)blockIdx.x * blockDim.x + threadIdx.x) * 4;
    long st = (long)gridDim.x * blockDim.x * 4;
    float4 z = make_float4(0.f, 0.f, 0.f, 0.f);
    for (; i < n; i += st) *(float4*)(p + i) = z;
}

__global__ void k_count_e(const int* __restrict__ ei, int* __restrict__ cnt) {
    int i = blockIdx.x * blockDim.x + threadIdx.x;
    int st = gridDim.x * blockDim.x;
    for (; i < 2 * NEDGE; i += st)
        atomicAdd(&cnt[((i >= NEDGE) ? NE : 0) + ei[2 * NEDGE + i]], 1);
}
__global__ void k_count_q(const int* __restrict__ qu, int* __restrict__ cnt) {
    int j = blockIdx.x * blockDim.x + threadIdx.x;
    int st = gridDim.x * blockDim.x;
    for (; j < 2 * NQ; j += st)
        atomicAdd(&cnt[((j >= NQ) ? NEDGE : 0) + qu[2 * QROW + j]], 1);
}
// fill qual inverse permutation only
__global__ void k_fill_q(const int* __restrict__ qu, int* __restrict__ cur,
                         int* __restrict__ qpos) {
    int j = blockIdx.x * blockDim.x + threadIdx.x;
    int st = gridDim.x * blockDim.x;
    for (; j < 2 * NQ; j += st) {
        int b = ((j >= NQ) ? NEDGE : 0) + qu[2 * QROW + j];
        int pos = atomicAdd(&cur[b], 1);
        qpos[j] = pos;
    }
}
// fill edge records at sorted positions
__global__ void k_fill_e(const int* __restrict__ ei, const int* __restrict__ et,
                         const float* __restrict__ dinv,
                         const int* __restrict__ qstart, const int* __restrict__ qcnt,
                         int* __restrict__ cur,
                         int* __restrict__ esrc, int* __restrict__ ety,
                         float* __restrict__ enm,
                         int* __restrict__ eqs, int* __restrict__ eqc) {
    int i = blockIdx.x * blockDim.x + threadIdx.x;
    int st = gridDim.x * blockDim.x;
    for (; i < 2 * NEDGE; i += st) {
        int d = (i >= NEDGE) ? 1 : 0;
        int e = i - d * NEDGE;
        int src = ei[i];
        int dst = ei[2 * NEDGE + i];
        int pos = atomicAdd(&cur[d * NE + dst], 1);
        esrc[pos] = src;
        ety[pos]  = et[i];
        enm[pos]  = dinv[d * NE + src] * dinv[d * NE + dst];
        eqs[pos]  = qstart[d * NEDGE + e];
        eqc[pos]  = qcnt[d * NEDGE + e];
    }
}
__global__ void k_dinv(const int* __restrict__ cnt, float* __restrict__ dinv) {
    int i = blockIdx.x * blockDim.x + threadIdx.x;
    int st = gridDim.x * blockDim.x;
    for (; i < 2 * NE; i += st) {
        int d = (i >= NE) ? 1 : 0;
        int n = i - d * NE;
        int c = cnt[(1 - d) * NE + n];
        dinv[i] = (c > 0) ? rsqrtf((float)c) : 0.f;
    }
}

// W fp32 [200][200] -> fp16 zero-padded [208][208]
__global__ void k_convW(const float* __restrict__ W, __half* __restrict__ dst) {
    int t = blockIdx.x * blockDim.x + threadIdx.x;
    if (t >= MSZ) return;
    int k = t / 208, n = t - k * 208;
    float v = (k < DIM && n < DIM) ? W[k * DIM + n] : 0.f;
    dst[t] = __float2half_rn(v);
}

// ---------------- two-level exclusive scan ----------------------------------
__global__ void k_scan1(const int* __restrict__ in, int* __restrict__ out,
                        int* __restrict__ part, int n) {
    __shared__ int s[1024];
    int t = threadIdx.x;
    int g = blockIdx.x * 1024 + t;
    int v = (g < n) ? in[g] : 0;
    s[t] = v;
    __syncthreads();
    for (int off = 1; off < 1024; off <<= 1) {
        int u = (t >= off) ? s[t - off] : 0;
        __syncthreads();
        s[t] += u;
        __syncthreads();
    }
    if (g < n) out[g] = s[t] - v;
    if (t == 1023 && part) part[blockIdx.x] = s[1023];
}
__global__ void k_scan_add(int* __restrict__ out, const int* __restrict__ psc, int n) {
    int g = blockIdx.x * 1024 + threadIdx.x;
    if (g < n) out[g] += psc[blockIdx.x];
}

// ---------------- fp16 tensor-core GEMM --------------------------------------
// C[rows,200] = compose(A)[rows,K] @ W[K,200]; K sections of 200.
// BM=64, 8 warps (4xM, 2xN); full-K A tile; double-buffered reg-staged W.

enum { M_QUAL = 0, M_FUSE = 1, M_PLAIN = 2 };

#define BM  64
#define AST 216       // half stride (432B = 27*16)
#define WST 216

__device__ __forceinline__ uint32_t s2u(const void* p) {
    return (uint32_t)__cvta_generic_to_shared(p);
}
__device__ __forceinline__ void mma16(float* c, uint32_t a0, uint32_t a1,
                                      uint32_t a2, uint32_t a3,
                                      uint32_t b0, uint32_t b1) {
    asm volatile(
        "mma.sync.aligned.m16n8k16.row.col.f32.f16.f16.f32 "
        "{%0,%1,%2,%3},{%4,%5,%6,%7},{%8,%9},{%0,%1,%2,%3};"
        : "+f"(c[0]), "+f"(c[1]), "+f"(c[2]), "+f"(c[3])
        : "r"(a0), "r"(a1), "r"(a2), "r"(a3), "r"(b0), "r"(b1));
}

template <int MODE>
__global__ void __launch_bounds__(256, 2)
k_gemm(const float* __restrict__ A,      // QUAL: x table | FUSE: nin | PLAIN: rows
       const float* __restrict__ B2,     // FUSE: nout
       const float* __restrict__ C3,     // FUSE: x (loop section)
       const float* __restrict__ relt,   // QUAL: rel table | FUSE: loop_rel
       const int* __restrict__ qe, const int* __restrict__ qr,
       const int* __restrict__ opos,     // QUAL: output row permutation
       const __half* __restrict__ Wh,    // fp16 padded; FUSE: 3 consecutive
       float* __restrict__ out,
       const float* __restrict__ bias,   // FUSE
       int nrows)
{
    __shared__ __align__(16) __half As[BM * AST];
    __shared__ __align__(16) __half Wb[2][16 * WST];
    const int tid = threadIdx.x;
    const int wid = tid >> 5, lane = tid & 31;
    const int wm = wid >> 1, wn = wid & 1;
    const int r4 = lane >> 2, kq = lane & 3;
    const int row0 = blockIdx.x * BM;
    const int NSEC = (MODE == M_FUSE) ? 3 : 1;
    // W chunk = 16 rows x 208 halfs = 416 contiguous uint4.
    const int k0a = tid / 26, sg0 = tid - k0a * 26;
    const int s1 = tid + 256;
    const int k1a = s1 / 26, sg1 = s1 - k1a * 26;
    const bool h2nd = (tid < 160);

    float acc[13][4];
#pragma unroll
    for (int f = 0; f < 13; f++)
        acc[f][0] = acc[f][1] = acc[f][2] = acc[f][3] = 0.f;

    for (int sec = 0; sec < NSEC; sec++) {
        __syncthreads();   // prev section's MMA reads of As/Wb complete
        // ---- fill full-K A tile (fp16), warp-per-row ----
        for (int rr = wid; rr < BM; rr += 8) {
            int gr = row0 + rr;
            const float4 *p1 = 0, *p2 = 0;
            bool valid = gr < nrows;
            if (valid) {
                if (MODE == M_QUAL) {
                    p1 = (const float4*)(A + (size_t)qe[gr] * DIM);
                    p2 = (const float4*)(relt + (size_t)qr[gr] * DIM);
                } else if (MODE == M_FUSE) {
                    if (sec == 0)      p1 = (const float4*)(A  + (size_t)gr * DIM);
                    else if (sec == 1) p1 = (const float4*)(B2 + (size_t)gr * DIM);
                    else { p1 = (const float4*)(C3 + (size_t)gr * DIM);
                           p2 = (const float4*)relt; }
                } else {
                    p1 = (const float4*)(A + (size_t)gr * DIM);
                }
            }
#pragma unroll
            for (int h = 0; h < 2; h++) {
                int k4 = lane + 32 * h;
                if (k4 >= 54) continue;              // 54*4 = 216 = AST (pad zeros)
                float4 v = make_float4(0.f, 0.f, 0.f, 0.f);
                if (valid && k4 < D4) {
                    v = p1[k4];
                    if (MODE == M_QUAL || (MODE == M_FUSE && sec == 2)) {
                        float4 r = p2[k4];
                        v.x *= r.x; v.y *= r.y; v.z *= r.z; v.w *= r.w;
                    }
                }
                union { uint2 u; __half2 h2[2]; } pk;
                pk.h2[0] = __floats2half2_rn(v.x, v.y);
                pk.h2[1] = __floats2half2_rn(v.z, v.w);
                *reinterpret_cast<uint2*>(&As[rr * AST + k4 * 4]) = pk.u;
            }
        }
        const __half* Wg = Wh + (size_t)sec * MSZ;
        const uint4* Wg4 = (const uint4*)Wg;

        // chunk 0 -> buf0; preload chunk 1 regs
        uint4 w0 = Wg4[tid];
        uint4 w1 = h2nd ? Wg4[s1] : make_uint4(0, 0, 0, 0);
        *(uint4*)&Wb[0][k0a * WST + sg0 * 8] = w0;
        if (h2nd) *(uint4*)&Wb[0][k1a * WST + sg1 * 8] = w1;
        w0 = Wg4[416 + tid];
        if (h2nd) w1 = Wg4[416 + s1];
        __syncthreads();        // As + buf0 visible

        for (int ks = 0; ks < 13; ks++) {
            const __half* wb = Wb[ks & 1];
            uint32_t a0, a1, a2, a3;
            uint32_t aaddr = s2u(&As[(wm * 16 + (lane & 15)) * AST
                                     + ks * 16 + ((lane >> 4) << 3)]);
            asm volatile("ldmatrix.sync.aligned.m8n8.x4.shared.b16 {%0,%1,%2,%3}, [%4];"
                         : "=r"(a0), "=r"(a1), "=r"(a2), "=r"(a3) : "r"(aaddr));
            int brow = ((lane >> 3) & 1) * 8 + (lane & 7);
#pragma unroll
            for (int fp = 0; fp < 6; fp++) {
                int n0 = wn * 104 + fp * 16;
                uint32_t b0, b1, b2, b3;
                uint32_t baddr = s2u(&wb[brow * WST + n0 + ((lane >> 4) << 3)]);
                asm volatile("ldmatrix.sync.aligned.m8n8.x4.trans.shared.b16 "
                             "{%0,%1,%2,%3}, [%4];"
                             : "=r"(b0), "=r"(b1), "=r"(b2), "=r"(b3) : "r"(baddr));
                mma16(acc[2 * fp], a0, a1, a2, a3, b0, b1);
                mma16(acc[2 * fp + 1], a0, a1, a2, a3, b2, b3);
            }
            {
                int n0 = wn * 104 + 96;
                uint32_t b0, b1;
                uint32_t baddr = s2u(&wb[brow * WST + n0]);
                asm volatile("ldmatrix.sync.aligned.m8n8.x2.trans.shared.b16 "
                             "{%0,%1}, [%2];"
                             : "=r"(b0), "=r"(b1) : "r"(baddr));
                mma16(acc[12], a0, a1, a2, a3, b0, b1);
            }
            if (ks < 12) {
                // store chunk ks+1 (safe: last reads of this buf were iter ks-1,
                // separated by the end-of-iter sync)
                __half* db = Wb[(ks + 1) & 1];
                *(uint4*)&db[k0a * WST + sg0 * 8] = w0;
                if (h2nd) *(uint4*)&db[k1a * WST + sg1 * 8] = w1;
                if (ks < 11) {      // LDG chunk ks+2, overlaps next iter's MMA
                    w0 = Wg4[(size_t)(ks + 2) * 416 + tid];
                    if (h2nd) w1 = Wg4[(size_t)(ks + 2) * 416 + s1];
                }
                __syncthreads();    // stores visible before iter ks+1 reads
            }
        }
    }

    // ---- epilogue ----
    int gr0 = row0 + wm * 16 + r4;
    int orow[2];
#pragma unroll
    for (int half = 0; half < 2; half++) {
        int gr = gr0 + 8 * half;
        orow[half] = (gr < nrows) ? ((MODE == M_QUAL) ? opos[gr] : gr) : -1;
    }
#pragma unroll
    for (int f = 0; f < 13; f++) {
        int col = wn * 104 + 8 * f + 2 * kq;
        if (col >= DIM) continue;
#pragma unroll
        for (int half = 0; half < 2; half++) {
            if (orow[half] < 0) continue;
            size_t o = (size_t)orow[half] * DIM + col;
            float v0 = acc[f][2 * half], v1 = acc[f][2 * half + 1];
            if (MODE == M_FUSE) {
                out[o]     = tanhf(v0 * (1.f / 3.f) + bias[col]);
                out[o + 1] = tanhf(v1 * (1.f / 3.f) + bias[col + 1]);
            } else {
                out[o] = v0; out[o + 1] = v1;
            }
        }
    }
}

// ---------------- CSR gather aggregation (record-based) ----------------------
__global__ void __launch_bounds__(256)
k_agg(const float* __restrict__ x, const float* __restrict__ relt,
      const int* __restrict__ e_start, const int* __restrict__ e_cnt,
      const int* __restrict__ esrc, const int* __restrict__ ety,
      const float* __restrict__ enm,
      const int* __restrict__ eqs, const int* __restrict__ eqc,
      const float* __restrict__ qproj,
      float* __restrict__ nin, float* __restrict__ nout)
{
    int w = (blockIdx.x * blockDim.x + threadIdx.x) >> 5;
    int lane = threadIdx.x & 31;
    if (w >= 2 * NE) return;
    int d = (w >= NE) ? 1 : 0;
    int n = w - d * NE;

    int c0 = lane;
    int c1 = lane + 32;
    bool has1 = (c1 < D4);

    float4 a0 = make_float4(0.f, 0.f, 0.f, 0.f);
    float4 a1 = a0;

    int beg = e_start[w], cnt = e_cnt[w];
    for (int idx = beg; idx < beg + cnt; idx++) {
        float nm = enm[idx];
        if (nm == 0.f) continue;
        int s = esrc[idx], ty = ety[idx];
        int qb = eqs[idx], qc = eqc[idx];
        const float4* xr = (const float4*)(x + (size_t)s * DIM);
        const float4* rr = (const float4*)(relt + (size_t)ty * DIM);
        float4 q0 = make_float4(0.f, 0.f, 0.f, 0.f);
        float4 q1 = q0;
        for (int t = qb; t < qb + qc; t++) {      // contiguous qproj rows
            const float4* qp = (const float4*)(qproj + (size_t)t * DIM);
            float4 v0 = qp[c0];
            q0.x += v0.x; q0.y += v0.y; q0.z += v0.z; q0.w += v0.w;
            if (has1) {
                float4 v1 = qp[c1];
                q1.x += v1.x; q1.y += v1.y; q1.z += v1.z; q1.w += v1.w;
            }
        }
        float4 xv = xr[c0], rv = rr[c0];
        a0.x += nm * xv.x * (ALPHA * rv.x + (1.f - ALPHA) * q0.x);
        a0.y += nm * xv.y * (ALPHA * rv.y + (1.f - ALPHA) * q0.y);
        a0.z += nm * xv.z * (ALPHA * rv.z + (1.f - ALPHA) * q0.z);
        a0.w += nm * xv.w * (ALPHA * rv.w + (1.f - ALPHA) * q0.w);
        if (has1) {
            float4 xw = xr[c1], rw = rr[c1];
            a1.x += nm * xw.x * (ALPHA * rw.x + (1.f - ALPHA) * q1.x);
            a1.y += nm * xw.y * (ALPHA * rw.y + (1.f - ALPHA) * q1.y);
            a1.z += nm * xw.z * (ALPHA * rw.z + (1.f - ALPHA) * q1.z);
            a1.w += nm * xw.w * (ALPHA * rw.w + (1.f - ALPHA) * q1.w);
        }
    }
    float4* ob = (float4*)((d ? nout : nin) + (size_t)n * DIM);
    ob[c0] = a0;
    if (has1) ob[c1] = a1;
}

// ---------------- final batched gathers --------------------------------------
__global__ void k_gather(const float* __restrict__ xf, const float* __restrict__ rf,
                         const int* __restrict__ ent_ix, const int* __restrict__ rel_ix,
                         const int* __restrict__ quals_ix, float* __restrict__ out)
{
    int warp = (blockIdx.x * blockDim.x + threadIdx.x) >> 5;
    int lane = threadIdx.x & 31;
    int nwarp = (gridDim.x * blockDim.x) >> 5;
    const int total = NB * 14;
    for (int r = warp; r < total; r += nwarp) {
        int b = r / 14, s = r - b * 14;
        const float* srcp;
        float* dstp;
        if (s == 0)      { srcp = xf + (size_t)ent_ix[b] * DIM;  dstp = out + OFF_SUB + (size_t)b * DIM; }
        else if (s == 1) { srcp = rf + (size_t)rel_ix[b] * DIM;  dstp = out + OFF_REL + (size_t)b * DIM; }
        else if (s < 8)  { int p = s - 2;
                           srcp = xf + (size_t)quals_ix[b * 2 * QP + 2 * p + 1] * DIM;
                           dstp = out + OFF_QO + ((size_t)b * QP + p) * DIM; }
        else             { int p = s - 8;
                           srcp = rf + (size_t)quals_ix[b * 2 * QP + 2 * p] * DIM;
                           dstp = out + OFF_QR + ((size_t)b * QP + p) * DIM; }
        for (int c = lane; c < D4; c += 32)
            ((float4*)dstp)[c] = ((const float4*)srcp)[c];
    }
}

// ---------------------------------------------------------------------------

extern "C" void kernel_launch(void* const* d_in, const int* in_sizes, int n_in,
                              void* d_out, int out_size)
{
    const float* ent        = (const float*)d_in[0];
    const float* rel0       = (const float*)d_in[1];
    const float* w_in[2]    = {(const float*)d_in[2],  (const float*)d_in[7]};
    const float* w_out[2]   = {(const float*)d_in[3],  (const float*)d_in[8]};
    const float* w_loop[2]  = {(const float*)d_in[4],  (const float*)d_in[9]};
    const float* w_rel[2]   = {(const float*)d_in[5],  (const float*)d_in[10]};
    const float* w_q[2]     = {(const float*)d_in[6],  (const float*)d_in[11]};
    const float* loop_rel[2]= {(const float*)d_in[12], (const float*)d_in[13]};
    const float* bias[2]    = {(const float*)d_in[14], (const float*)d_in[15]};
    const int* ei       = (const int*)d_in[16];
    const int* et       = (const int*)d_in[17];
    const int* qu       = (const int*)d_in[18];
    const int* ent_ix   = (const int*)d_in[19];
    const int* rel_ix   = (const int*)d_in[20];
    const int* quals_ix = (const int*)d_in[21];
    float* out = (float*)d_out;

    float *qproj, *nin, *nout, *x1, *r1, *dinv, *enm;
    __half* wh;
    int *ecnt, *estart, *ecur, *qcnt, *qstart, *qcur, *qpos;
    int *esrc, *ety, *eqs, *eqc, *part, *psc;
    cudaGetSymbolAddress((void**)&qproj,  g_qproj);
    cudaGetSymbolAddress((void**)&nin,    g_nin);
    cudaGetSymbolAddress((void**)&nout,   g_nout);
    cudaGetSymbolAddress((void**)&x1,     g_x1);
    cudaGetSymbolAddress((void**)&r1,     g_r1);
    cudaGetSymbolAddress((void**)&dinv,   g_dinv);
    cudaGetSymbolAddress((void**)&enm,    g_enm);
    cudaGetSymbolAddress((void**)&wh,     g_wh);
    cudaGetSymbolAddress((void**)&ecnt,   gi_ecnt);
    cudaGetSymbolAddress((void**)&estart, gi_estart);
    cudaGetSymbolAddress((void**)&ecur,   gi_ecur);
    cudaGetSymbolAddress((void**)&qcnt,   gi_qcnt);
    cudaGetSymbolAddress((void**)&qstart, gi_qstart);
    cudaGetSymbolAddress((void**)&qcur,   gi_qcur);
    cudaGetSymbolAddress((void**)&qpos,   gi_qpos);
    cudaGetSymbolAddress((void**)&esrc,   gi_esrc);
    cudaGetSymbolAddress((void**)&ety,    gi_ety);
    cudaGetSymbolAddress((void**)&eqs,    gi_eqs);
    cudaGetSymbolAddress((void**)&eqc,    gi_eqc);
    cudaGetSymbolAddress((void**)&part,   gi_part);
    cudaGetSymbolAddress((void**)&psc,    gi_psc);

    // ---- fp16 weight conversion: per layer {w_in,w_out,w_loop,w_q,w_rel}
    int cb = (MSZ + 255) / 256;
    for (int L = 0; L < 2; L++) {
        k_convW<<<cb, 256>>>(w_in[L],   wh + (size_t)(L * 5 + 0) * MSZ);
        k_convW<<<cb, 256>>>(w_out[L],  wh + (size_t)(L * 5 + 1) * MSZ);
        k_convW<<<cb, 256>>>(w_loop[L], wh + (size_t)(L * 5 + 2) * MSZ);
        k_convW<<<cb, 256>>>(w_q[L],    wh + (size_t)(L * 5 + 3) * MSZ);
        k_convW<<<cb, 256>>>(w_rel[L],  wh + (size_t)(L * 5 + 4) * MSZ);
    }

    // ---- CSR build (records) ----
    k_zero<<<256, 256>>>((float*)ecnt, 2L * NE);
    k_zero<<<512, 256>>>((float*)qcnt, 2L * NEDGE);
    k_count_e<<<2048, 256>>>(ei, ecnt);
    k_count_q<<<2048, 256>>>(qu, qcnt);

    int nbE = (2 * NE + 1023) / 1024;
    k_scan1<<<nbE, 1024>>>(ecnt, estart, part, 2 * NE);
    k_scan1<<<1, 1024>>>(part, psc, (int*)0, nbE);
    k_scan_add<<<nbE, 1024>>>(estart, psc, 2 * NE);

    int nbQ = (2 * NEDGE + 1023) / 1024;
    k_scan1<<<nbQ, 1024>>>(qcnt, qstart, part, 2 * NEDGE);
    k_scan1<<<1, 1024>>>(part, psc, (int*)0, nbQ);
    k_scan_add<<<nbQ, 1024>>>(qstart, psc, 2 * NEDGE);

    k_dinv<<<512, 256>>>(ecnt, dinv);

    cudaMemcpyAsync(qcur, qstart, 2L * NEDGE * sizeof(int), cudaMemcpyDeviceToDevice, 0);
    k_fill_q<<<2048, 256>>>(qu, qcur, qpos);

    cudaMemcpyAsync(ecur, estart, 2L * NE * sizeof(int), cudaMemcpyDeviceToDevice, 0);
    k_fill_e<<<2048, 256>>>(ei, et, dinv, qstart, qcnt, ecur,
                            esrc, ety, enm, eqs, eqc);

    float* xf = out + OFF_X;
    float* rf = out + OFF_R;

    for (int L = 0; L < 2; L++) {
        const float* xin = L ? (const float*)x1 : ent;
        const float* rin = L ? (const float*)r1 : rel0;
        float* xout = L ? xf : x1;
        float* rout = L ? rf : r1;

        // qproj[qpos[j]] = (x[q_e[j]] ⊙ rel[q_r[j]]) @ w_q   (800k rows)
        k_gemm<M_QUAL><<<(QROW + BM - 1) / BM, 256>>>(
            xin, 0, 0, rin, qu + QROW, qu, qpos,
            wh + (size_t)(L * 5 + 3) * MSZ, qproj, 0, QROW);

        // both-direction record-based CSR gather -> nin / nout
        k_agg<<<(2 * NE * 32 + 255) / 256, 256>>>(
            xin, rin, estart, ecnt, esrc, ety, enm, eqs, eqc,
            qproj, nin, nout);

        // x_out = tanh(([nin|nout|x⊙loop] @ [w_in;w_out;w_loop])/3 + b)
        k_gemm<M_FUSE><<<(NE + BM - 1) / BM, 256>>>(
            nin, nout, xin, loop_rel[L], 0, 0, 0,
            wh + (size_t)(L * 5 + 0) * MSZ, xout, bias[L], NE);

        // r_out = r_in @ w_rel
        k_gemm<M_PLAIN><<<(NR + BM - 1) / BM, 256>>>(
            rin, 0, 0, 0, 0, 0, 0,
            wh + (size_t)(L * 5 + 4) * MSZ, rout, 0, NR);
    }

    k_gather<<<7168, 256>>>(xf, rf, ent_ix, rel_ix, quals_ix, out);
}

// round 12
// speedup vs baseline: 1.4234x; 1.1871x over previous
#include <cuda_runtime.h>
#include <cuda_fp16.h>
#include <math.h>
#include <stdint.h>

// ---------------------------------------------------------------------------
// HypRelEncoder — round 12 (traffic cuts):
//  * qproj stored fp16 (halves QUAL-write + k_agg-read traffic)
//  * nin/nout stored fp16 (identical numerics; rounding moved into k_agg)
//  * packed int4 edge records + next-record prefetch in k_agg
//  * everything else identical to passing round-11 kernel
// ---------------------------------------------------------------------------

#define NE    200000
#define DIM   200
#define D4    50          // DIM / 4
#define NEDGE 500000
#define NQ    400000
#define QROW  (2*NQ)      // 800000
#define NR    200
#define NB    4096
#define QP    6
#define ALPHA 0.8f
#define MSZ   (208*208)   // padded fp16 weight matrix size

#define OFF_SUB 0
#define OFF_REL (NB*DIM)
#define OFF_QO  (2*NB*DIM)
#define OFF_QR  (OFF_QO + NB*QP*DIM)
#define OFF_X   (OFF_QR + NB*QP*DIM)
#define OFF_R   (OFF_X + NE*DIM)

// ---------------- device scratch -------------------------------------------
__device__ __align__(16) __half g_qproj[(size_t)QROW * DIM];  // 320 MB, fp16, CSR order
__device__ __align__(16) __half g_ninh [(size_t)NE * DIM];    // 80 MB fp16
__device__ __align__(16) __half g_nouth[(size_t)NE * DIM];    // 80 MB fp16
__device__ float g_x1  [(size_t)NE * DIM];
__device__ float g_r1[NR * DIM];
__device__ float g_dinv[2 * NE];
__device__ __align__(16) __half g_wh[(size_t)10 * MSZ];       // padded fp16 weights
__device__ int   gi_ecnt[2 * NE];
__device__ int   gi_estart[2 * NE];
__device__ int   gi_ecur[2 * NE];
__device__ int   gi_qcnt[2 * NEDGE];
__device__ int   gi_qstart[2 * NEDGE];
__device__ int   gi_qcur[2 * NEDGE];
__device__ int   gi_qpos[2 * NQ];                // qual j -> sorted position
__device__ int4  gi_erec[2 * NEDGE];             // (src, ty, qstart, qcnt) sorted
__device__ float g_enm [2 * NEDGE];              // per-edge norm, sorted
__device__ int   gi_part[1024];
__device__ int   gi_psc[1024];

// ---------------- small helpers --------------------------------------------
__global__ void k_zero(float* __restrict__ p, long n) {
    long i = ((long)blockIdx.x * blockDim.x + threadIdx.x) * 4;
    long st = (long)gridDim.x * blockDim.x * 4;
    float4 z = make_float4(0.f, 0.f, 0.f, 0.f);
    for (; i < n; i += st) *(float4*)(p + i) = z;
}

__global__ void k_count_e(const int* __restrict__ ei, int* __restrict__ cnt) {
    int i = blockIdx.x * blockDim.x + threadIdx.x;
    int st = gridDim.x * blockDim.x;
    for (; i < 2 * NEDGE; i += st)
        atomicAdd(&cnt[((i >= NEDGE) ? NE : 0) + ei[2 * NEDGE + i]], 1);
}
__global__ void k_count_q(const int* __restrict__ qu, int* __restrict__ cnt) {
    int j = blockIdx.x * blockDim.x + threadIdx.x;
    int st = gridDim.x * blockDim.x;
    for (; j < 2 * NQ; j += st)
        atomicAdd(&cnt[((j >= NQ) ? NEDGE : 0) + qu[2 * QROW + j]], 1);
}
__global__ void k_fill_q(const int* __restrict__ qu, int* __restrict__ cur,
                         int* __restrict__ qpos) {
    int j = blockIdx.x * blockDim.x + threadIdx.x;
    int st = gridDim.x * blockDim.x;
    for (; j < 2 * NQ; j += st) {
        int b = ((j >= NQ) ? NEDGE : 0) + qu[2 * QROW + j];
        int pos = atomicAdd(&cur[b], 1);
        qpos[j] = pos;
    }
}
__global__ void k_fill_e(const int* __restrict__ ei, const int* __restrict__ et,
                         const float* __restrict__ dinv,
                         const int* __restrict__ qstart, const int* __restrict__ qcnt,
                         int* __restrict__ cur,
                         int4* __restrict__ erec, float* __restrict__ enm) {
    int i = blockIdx.x * blockDim.x + threadIdx.x;
    int st = gridDim.x * blockDim.x;
    for (; i < 2 * NEDGE; i += st) {
        int d = (i >= NEDGE) ? 1 : 0;
        int e = i - d * NEDGE;
        int src = ei[i];
        int dst = ei[2 * NEDGE + i];
        int pos = atomicAdd(&cur[d * NE + dst], 1);
        int4 r;
        r.x = src;
        r.y = et[i];
        r.z = qstart[d * NEDGE + e];
        r.w = qcnt[d * NEDGE + e];
        erec[pos] = r;
        enm[pos] = dinv[d * NE + src] * dinv[d * NE + dst];
    }
}
__global__ void k_dinv(const int* __restrict__ cnt, float* __restrict__ dinv) {
    int i = blockIdx.x * blockDim.x + threadIdx.x;
    int st = gridDim.x * blockDim.x;
    for (; i < 2 * NE; i += st) {
        int d = (i >= NE) ? 1 : 0;
        int n = i - d * NE;
        int c = cnt[(1 - d) * NE + n];
        dinv[i] = (c > 0) ? rsqrtf((float)c) : 0.f;
    }
}

// W fp32 [200][200] -> fp16 zero-padded [208][208]
__global__ void k_convW(const float* __restrict__ W, __half* __restrict__ dst) {
    int t = blockIdx.x * blockDim.x + threadIdx.x;
    if (t >= MSZ) return;
    int k = t / 208, n = t - k * 208;
    float v = (k < DIM && n < DIM) ? W[k * DIM + n] : 0.f;
    dst[t] = __float2half_rn(v);
}

// ---------------- two-level exclusive scan ----------------------------------
__global__ void k_scan1(const int* __restrict__ in, int* __restrict__ out,
                        int* __restrict__ part, int n) {
    __shared__ int s[1024];
    int t = threadIdx.x;
    int g = blockIdx.x * 1024 + t;
    int v = (g < n) ? in[g] : 0;
    s[t] = v;
    __syncthreads();
    for (int off = 1; off < 1024; off <<= 1) {
        int u = (t >= off) ? s[t - off] : 0;
        __syncthreads();
        s[t] += u;
        __syncthreads();
    }
    if (g < n) out[g] = s[t] - v;
    if (t == 1023 && part) part[blockIdx.x] = s[1023];
}
__global__ void k_scan_add(int* __restrict__ out, const int* __restrict__ psc, int n) {
    int g = blockIdx.x * 1024 + threadIdx.x;
    if (g < n) out[g] += psc[blockIdx.x];
}

// ---------------- fp16 tensor-core GEMM --------------------------------------
// C[rows,200] = compose(A)[rows,K] @ W[K,200]; K sections of 200.
// BM=64, 8 warps (4xM, 2xN); full-K A tile; double-buffered reg-staged W.

enum { M_QUAL = 0, M_FUSE = 1, M_PLAIN = 2 };

#define BM  64
#define AST 216       // half stride (432B = 27*16)
#define WST 216

__device__ __forceinline__ uint32_t s2u(const void* p) {
    return (uint32_t)__cvta_generic_to_shared(p);
}
__device__ __forceinline__ void mma16(float* c, uint32_t a0, uint32_t a1,
                                      uint32_t a2, uint32_t a3,
                                      uint32_t b0, uint32_t b1) {
    asm volatile(
        "mma.sync.aligned.m16n8k16.row.col.f32.f16.f16.f32 "
        "{%0,%1,%2,%3},{%4,%5,%6,%7},{%8,%9},{%0,%1,%2,%3};"
        : "+f"(c[0]), "+f"(c[1]), "+f"(c[2]), "+f"(c[3])
        : "r"(a0), "r"(a1), "r"(a2), "r"(a3), "r"(b0), "r"(b1));
}

template <int MODE>
__global__ void __launch_bounds__(256, 2)
k_gemm(const float* __restrict__ A,      // QUAL: x table | PLAIN: rows
       const __half* __restrict__ hA,    // FUSE: nin (fp16)
       const __half* __restrict__ hB2,   // FUSE: nout (fp16)
       const float* __restrict__ C3,     // FUSE: x (loop section)
       const float* __restrict__ relt,   // QUAL: rel table | FUSE: loop_rel
       const int* __restrict__ qe, const int* __restrict__ qr,
       const int* __restrict__ opos,     // QUAL: output row permutation
       const __half* __restrict__ Wh,    // fp16 padded; FUSE: 3 consecutive
       float* __restrict__ out,          // FUSE / PLAIN output
       __half* __restrict__ hqout,       // QUAL output (fp16)
       const float* __restrict__ bias,   // FUSE
       int nrows)
{
    __shared__ __align__(16) __half As[BM * AST];
    __shared__ __align__(16) __half Wb[2][16 * WST];
    const int tid = threadIdx.x;
    const int wid = tid >> 5, lane = tid & 31;
    const int wm = wid >> 1, wn = wid & 1;
    const int r4 = lane >> 2, kq = lane & 3;
    const int row0 = blockIdx.x * BM;
    const int NSEC = (MODE == M_FUSE) ? 3 : 1;
    // W chunk = 16 rows x 208 halfs = 416 contiguous uint4.
    const int k0a = tid / 26, sg0 = tid - k0a * 26;
    const int s1 = tid + 256;
    const int k1a = s1 / 26, sg1 = s1 - k1a * 26;
    const bool h2nd = (tid < 160);

    float acc[13][4];
#pragma unroll
    for (int f = 0; f < 13; f++)
        acc[f][0] = acc[f][1] = acc[f][2] = acc[f][3] = 0.f;

    for (int sec = 0; sec < NSEC; sec++) {
        __syncthreads();   // prev section's MMA reads of As/Wb complete
        // ---- fill full-K A tile (fp16), warp-per-row ----
        for (int rr = wid; rr < BM; rr += 8) {
            int gr = row0 + rr;
            bool valid = gr < nrows;
            if (MODE == M_FUSE && sec < 2) {
                // fp16 rows: plain uint2 copy (4 halfs per lane slot)
                const __half* hrow = (sec == 0 ? hA : hB2) + (size_t)gr * DIM;
#pragma unroll
                for (int h = 0; h < 2; h++) {
                    int k4 = lane + 32 * h;
                    if (k4 >= 54) continue;
                    uint2 v = make_uint2(0, 0);
                    if (valid && k4 < D4)
                        v = ((const uint2*)hrow)[k4];
                    *reinterpret_cast<uint2*>(&As[rr * AST + k4 * 4]) = v;
                }
            } else {
                const float4 *p1 = 0, *p2 = 0;
                if (valid) {
                    if (MODE == M_QUAL) {
                        p1 = (const float4*)(A + (size_t)qe[gr] * DIM);
                        p2 = (const float4*)(relt + (size_t)qr[gr] * DIM);
                    } else if (MODE == M_FUSE) {   // sec == 2: loop section
                        p1 = (const float4*)(C3 + (size_t)gr * DIM);
                        p2 = (const float4*)relt;
                    } else {
                        p1 = (const float4*)(A + (size_t)gr * DIM);
                    }
                }
#pragma unroll
                for (int h = 0; h < 2; h++) {
                    int k4 = lane + 32 * h;
                    if (k4 >= 54) continue;          // 54*4 = 216 = AST
                    float4 v = make_float4(0.f, 0.f, 0.f, 0.f);
                    if (valid && k4 < D4) {
                        v = p1[k4];
                        if (MODE == M_QUAL || MODE == M_FUSE) {
                            float4 r = p2[k4];
                            v.x *= r.x; v.y *= r.y; v.z *= r.z; v.w *= r.w;
                        }
                    }
                    union { uint2 u; __half2 h2[2]; } pk;
                    pk.h2[0] = __floats2half2_rn(v.x, v.y);
                    pk.h2[1] = __floats2half2_rn(v.z, v.w);
                    *reinterpret_cast<uint2*>(&As[rr * AST + k4 * 4]) = pk.u;
                }
            }
        }
        const __half* Wg = Wh + (size_t)sec * MSZ;
        const uint4* Wg4 = (const uint4*)Wg;

        // chunk 0 -> buf0; preload chunk 1 regs
        uint4 w0 = Wg4[tid];
        uint4 w1 = h2nd ? Wg4[s1] : make_uint4(0, 0, 0, 0);
        *(uint4*)&Wb[0][k0a * WST + sg0 * 8] = w0;
        if (h2nd) *(uint4*)&Wb[0][k1a * WST + sg1 * 8] = w1;
        w0 = Wg4[416 + tid];
        if (h2nd) w1 = Wg4[416 + s1];
        __syncthreads();        // As + buf0 visible

        for (int ks = 0; ks < 13; ks++) {
            const __half* wb = Wb[ks & 1];
            uint32_t a0, a1, a2, a3;
            uint32_t aaddr = s2u(&As[(wm * 16 + (lane & 15)) * AST
                                     + ks * 16 + ((lane >> 4) << 3)]);
            asm volatile("ldmatrix.sync.aligned.m8n8.x4.shared.b16 {%0,%1,%2,%3}, [%4];"
                         : "=r"(a0), "=r"(a1), "=r"(a2), "=r"(a3) : "r"(aaddr));
            int brow = ((lane >> 3) & 1) * 8 + (lane & 7);
#pragma unroll
            for (int fp = 0; fp < 6; fp++) {
                int n0 = wn * 104 + fp * 16;
                uint32_t b0, b1, b2, b3;
                uint32_t baddr = s2u(&wb[brow * WST + n0 + ((lane >> 4) << 3)]);
                asm volatile("ldmatrix.sync.aligned.m8n8.x4.trans.shared.b16 "
                             "{%0,%1,%2,%3}, [%4];"
                             : "=r"(b0), "=r"(b1), "=r"(b2), "=r"(b3) : "r"(baddr));
                mma16(acc[2 * fp], a0, a1, a2, a3, b0, b1);
                mma16(acc[2 * fp + 1], a0, a1, a2, a3, b2, b3);
            }
            {
                int n0 = wn * 104 + 96;
                uint32_t b0, b1;
                uint32_t baddr = s2u(&wb[brow * WST + n0]);
                asm volatile("ldmatrix.sync.aligned.m8n8.x2.trans.shared.b16 "
                             "{%0,%1}, [%2];"
                             : "=r"(b0), "=r"(b1) : "r"(baddr));
                mma16(acc[12], a0, a1, a2, a3, b0, b1);
            }
            if (ks < 12) {
                __half* db = Wb[(ks + 1) & 1];
                *(uint4*)&db[k0a * WST + sg0 * 8] = w0;
                if (h2nd) *(uint4*)&db[k1a * WST + sg1 * 8] = w1;
                if (ks < 11) {
                    w0 = Wg4[(size_t)(ks + 2) * 416 + tid];
                    if (h2nd) w1 = Wg4[(size_t)(ks + 2) * 416 + s1];
                }
                __syncthreads();
            }
        }
    }

    // ---- epilogue ----
    int gr0 = row0 + wm * 16 + r4;
    int orow[2];
#pragma unroll
    for (int half = 0; half < 2; half++) {
        int gr = gr0 + 8 * half;
        orow[half] = (gr < nrows) ? ((MODE == M_QUAL) ? opos[gr] : gr) : -1;
    }
#pragma unroll
    for (int f = 0; f < 13; f++) {
        int col = wn * 104 + 8 * f + 2 * kq;
        if (col >= DIM) continue;
#pragma unroll
        for (int half = 0; half < 2; half++) {
            if (orow[half] < 0) continue;
            size_t o = (size_t)orow[half] * DIM + col;
            float v0 = acc[f][2 * half], v1 = acc[f][2 * half + 1];
            if (MODE == M_QUAL) {
                *reinterpret_cast<__half2*>(&hqout[o]) = __floats2half2_rn(v0, v1);
            } else if (MODE == M_FUSE) {
                out[o]     = tanhf(v0 * (1.f / 3.f) + bias[col]);
                out[o + 1] = tanhf(v1 * (1.f / 3.f) + bias[col + 1]);
            } else {
                out[o] = v0; out[o + 1] = v1;
            }
        }
    }
}

// ---------------- CSR gather aggregation (record-based, fp16 qproj/out) ------
__global__ void __launch_bounds__(256)
k_agg(const float* __restrict__ x, const float* __restrict__ relt,
      const int* __restrict__ e_start, const int* __restrict__ e_cnt,
      const int4* __restrict__ erec, const float* __restrict__ enm,
      const __half* __restrict__ qproj,
      __half* __restrict__ ninh, __half* __restrict__ nouth)
{
    int w = (blockIdx.x * blockDim.x + threadIdx.x) >> 5;
    int lane = threadIdx.x & 31;
    if (w >= 2 * NE) return;
    int d = (w >= NE) ? 1 : 0;
    int n = w - d * NE;

    int c0 = lane;
    int c1 = lane + 32;
    bool has1 = (c1 < D4);

    float4 a0 = make_float4(0.f, 0.f, 0.f, 0.f);
    float4 a1 = a0;

    int beg = e_start[w];
    int end = beg + e_cnt[w];
    if (beg < end) {
        int4 rec = erec[beg];
        float nm = enm[beg];
        for (int idx = beg; idx < end; idx++) {
            int4 rec_n = rec;
            float nm_n = nm;
            if (idx + 1 < end) {       // prefetch next record (hides its latency)
                rec_n = erec[idx + 1];
                nm_n = enm[idx + 1];
            }
            if (nm != 0.f) {
                const float4* xr = (const float4*)(x + (size_t)rec.x * DIM);
                const float4* rr = (const float4*)(relt + (size_t)rec.y * DIM);
                float4 q0 = make_float4(0.f, 0.f, 0.f, 0.f);
                float4 q1 = q0;
                for (int t = rec.z; t < rec.z + rec.w; t++) {   // contiguous rows
                    const uint2* qp = (const uint2*)(qproj + (size_t)t * DIM);
                    uint2 u0 = qp[c0];
                    float2 f0 = __half22float2(*reinterpret_cast<__half2*>(&u0.x));
                    float2 f1 = __half22float2(*reinterpret_cast<__half2*>(&u0.y));
                    q0.x += f0.x; q0.y += f0.y; q0.z += f1.x; q0.w += f1.y;
                    if (has1) {
                        uint2 u1 = qp[c1];
                        float2 g0 = __half22float2(*reinterpret_cast<__half2*>(&u1.x));
                        float2 g1 = __half22float2(*reinterpret_cast<__half2*>(&u1.y));
                        q1.x += g0.x; q1.y += g0.y; q1.z += g1.x; q1.w += g1.y;
                    }
                }
                float4 xv = xr[c0], rv = rr[c0];
                a0.x += nm * xv.x * (ALPHA * rv.x + (1.f - ALPHA) * q0.x);
                a0.y += nm * xv.y * (ALPHA * rv.y + (1.f - ALPHA) * q0.y);
                a0.z += nm * xv.z * (ALPHA * rv.z + (1.f - ALPHA) * q0.z);
                a0.w += nm * xv.w * (ALPHA * rv.w + (1.f - ALPHA) * q0.w);
                if (has1) {
                    float4 xw = xr[c1], rw = rr[c1];
                    a1.x += nm * xw.x * (ALPHA * rw.x + (1.f - ALPHA) * q1.x);
                    a1.y += nm * xw.y * (ALPHA * rw.y + (1.f - ALPHA) * q1.y);
                    a1.z += nm * xw.z * (ALPHA * rw.z + (1.f - ALPHA) * q1.z);
                    a1.w += nm * xw.w * (ALPHA * rw.w + (1.f - ALPHA) * q1.w);
                }
            }
            rec = rec_n;
            nm = nm_n;
        }
    }
    __half* ob = (d ? nouth : ninh) + (size_t)n * DIM;
    union { uint2 u; __half2 h2[2]; } s0;
    s0.h2[0] = __floats2half2_rn(a0.x, a0.y);
    s0.h2[1] = __floats2half2_rn(a0.z, a0.w);
    ((uint2*)ob)[c0] = s0.u;
    if (has1) {
        union { uint2 u; __half2 h2[2]; } s1;
        s1.h2[0] = __floats2half2_rn(a1.x, a1.y);
        s1.h2[1] = __floats2half2_rn(a1.z, a1.w);
        ((uint2*)ob)[c1] = s1.u;
    }
}

// ---------------- final batched gathers --------------------------------------
__global__ void k_gather(const float* __restrict__ xf, const float* __restrict__ rf,
                         const int* __restrict__ ent_ix, const int* __restrict__ rel_ix,
                         const int* __restrict__ quals_ix, float* __restrict__ out)
{
    int warp = (blockIdx.x * blockDim.x + threadIdx.x) >> 5;
    int lane = threadIdx.x & 31;
    int nwarp = (gridDim.x * blockDim.x) >> 5;
    const int total = NB * 14;
    for (int r = warp; r < total; r += nwarp) {
        int b = r / 14, s = r - b * 14;
        const float* srcp;
        float* dstp;
        if (s == 0)      { srcp = xf + (size_t)ent_ix[b] * DIM;  dstp = out + OFF_SUB + (size_t)b * DIM; }
        else if (s == 1) { srcp = rf + (size_t)rel_ix[b] * DIM;  dstp = out + OFF_REL + (size_t)b * DIM; }
        else if (s < 8)  { int p = s - 2;
                           srcp = xf + (size_t)quals_ix[b * 2 * QP + 2 * p + 1] * DIM;
                           dstp = out + OFF_QO + ((size_t)b * QP + p) * DIM; }
        else             { int p = s - 8;
                           srcp = rf + (size_t)quals_ix[b * 2 * QP + 2 * p] * DIM;
                           dstp = out + OFF_QR + ((size_t)b * QP + p) * DIM; }
        for (int c = lane; c < D4; c += 32)
            ((float4*)dstp)[c] = ((const float4*)srcp)[c];
    }
}

// ---------------------------------------------------------------------------

extern "C" void kernel_launch(void* const* d_in, const int* in_sizes, int n_in,
                              void* d_out, int out_size)
{
    const float* ent        = (const float*)d_in[0];
    const float* rel0       = (const float*)d_in[1];
    const float* w_in[2]    = {(const float*)d_in[2],  (const float*)d_in[7]};
    const float* w_out[2]   = {(const float*)d_in[3],  (const float*)d_in[8]};
    const float* w_loop[2]  = {(const float*)d_in[4],  (const float*)d_in[9]};
    const float* w_rel[2]   = {(const float*)d_in[5],  (const float*)d_in[10]};
    const float* w_q[2]     = {(const float*)d_in[6],  (const float*)d_in[11]};
    const float* loop_rel[2]= {(const float*)d_in[12], (const float*)d_in[13]};
    const float* bias[2]    = {(const float*)d_in[14], (const float*)d_in[15]};
    const int* ei       = (const int*)d_in[16];
    const int* et       = (const int*)d_in[17];
    const int* qu       = (const int*)d_in[18];
    const int* ent_ix   = (const int*)d_in[19];
    const int* rel_ix   = (const int*)d_in[20];
    const int* quals_ix = (const int*)d_in[21];
    float* out = (float*)d_out;

    float *x1, *r1, *dinv, *enm;
    __half *qproj, *ninh, *nouth, *wh;
    int *ecnt, *estart, *ecur, *qcnt, *qstart, *qcur, *qpos, *part, *psc;
    int4* erec;
    cudaGetSymbolAddress((void**)&qproj,  g_qproj);
    cudaGetSymbolAddress((void**)&ninh,   g_ninh);
    cudaGetSymbolAddress((void**)&nouth,  g_nouth);
    cudaGetSymbolAddress((void**)&x1,     g_x1);
    cudaGetSymbolAddress((void**)&r1,     g_r1);
    cudaGetSymbolAddress((void**)&dinv,   g_dinv);
    cudaGetSymbolAddress((void**)&enm,    g_enm);
    cudaGetSymbolAddress((void**)&wh,     g_wh);
    cudaGetSymbolAddress((void**)&ecnt,   gi_ecnt);
    cudaGetSymbolAddress((void**)&estart, gi_estart);
    cudaGetSymbolAddress((void**)&ecur,   gi_ecur);
    cudaGetSymbolAddress((void**)&qcnt,   gi_qcnt);
    cudaGetSymbolAddress((void**)&qstart, gi_qstart);
    cudaGetSymbolAddress((void**)&qcur,   gi_qcur);
    cudaGetSymbolAddress((void**)&qpos,   gi_qpos);
    cudaGetSymbolAddress((void**)&erec,   gi_erec);
    cudaGetSymbolAddress((void**)&part,   gi_part);
    cudaGetSymbolAddress((void**)&psc,    gi_psc);

    // ---- fp16 weight conversion: per layer {w_in,w_out,w_loop,w_q,w_rel}
    int cb = (MSZ + 255) / 256;
    for (int L = 0; L < 2; L++) {
        k_convW<<<cb, 256>>>(w_in[L],   wh + (size_t)(L * 5 + 0) * MSZ);
        k_convW<<<cb, 256>>>(w_out[L],  wh + (size_t)(L * 5 + 1) * MSZ);
        k_convW<<<cb, 256>>>(w_loop[L], wh + (size_t)(L * 5 + 2) * MSZ);
        k_convW<<<cb, 256>>>(w_q[L],    wh + (size_t)(L * 5 + 3) * MSZ);
        k_convW<<<cb, 256>>>(w_rel[L],  wh + (size_t)(L * 5 + 4) * MSZ);
    }

    // ---- CSR build (records) ----
    k_zero<<<256, 256>>>((float*)ecnt, 2L * NE);
    k_zero<<<512, 256>>>((float*)qcnt, 2L * NEDGE);
    k_count_e<<<2048, 256>>>(ei, ecnt);
    k_count_q<<<2048, 256>>>(qu, qcnt);

    int nbE = (2 * NE + 1023) / 1024;
    k_scan1<<<nbE, 1024>>>(ecnt, estart, part, 2 * NE);
    k_scan1<<<1, 1024>>>(part, psc, (int*)0, nbE);
    k_scan_add<<<nbE, 1024>>>(estart, psc, 2 * NE);

    int nbQ = (2 * NEDGE + 1023) / 1024;
    k_scan1<<<nbQ, 1024>>>(qcnt, qstart, part, 2 * NEDGE);
    k_scan1<<<1, 1024>>>(part, psc, (int*)0, nbQ);
    k_scan_add<<<nbQ, 1024>>>(qstart, psc, 2 * NEDGE);

    k_dinv<<<512, 256>>>(ecnt, dinv);

    cudaMemcpyAsync(qcur, qstart, 2L * NEDGE * sizeof(int), cudaMemcpyDeviceToDevice, 0);
    k_fill_q<<<2048, 256>>>(qu, qcur, qpos);

    cudaMemcpyAsync(ecur, estart, 2L * NE * sizeof(int), cudaMemcpyDeviceToDevice, 0);
    k_fill_e<<<2048, 256>>>(ei, et, dinv, qstart, qcnt, ecur, erec, enm);

    float* xf = out + OFF_X;
    float* rf = out + OFF_R;

    for (int L = 0; L < 2; L++) {
        const float* xin = L ? (const float*)x1 : ent;
        const float* rin = L ? (const float*)r1 : rel0;
        float* xout = L ? xf : x1;
        float* rout = L ? rf : r1;

        // qproj[qpos[j]] = fp16((x[q_e[j]] ⊙ rel[q_r[j]]) @ w_q)   (800k rows)
        k_gemm<M_QUAL><<<(QROW + BM - 1) / BM, 256>>>(
            xin, 0, 0, 0, rin, qu + QROW, qu, qpos,
            wh + (size_t)(L * 5 + 3) * MSZ, 0, qproj, 0, QROW);

        // both-direction record-based CSR gather -> ninh / nouth (fp16)
        k_agg<<<(2 * NE * 32 + 255) / 256, 256>>>(
            xin, rin, estart, ecnt, erec, enm, qproj, ninh, nouth);

        // x_out = tanh(([nin|nout|x⊙loop] @ [w_in;w_out;w_loop])/3 + b)
        k_gemm<M_FUSE><<<(NE + BM - 1) / BM, 256>>>(
            0, ninh, nouth, xin, loop_rel[L], 0, 0, 0,
            wh + (size_t)(L * 5 + 0) * MSZ, xout, 0, bias[L], NE);

        // r_out = r_in @ w_rel
        k_gemm<M_PLAIN><<<(NR + BM - 1) / BM, 256>>>(
            rin, 0, 0, 0, 0, 0, 0, 0,
            wh + (size_t)(L * 5 + 4) * MSZ, rout, 0, 0, NR);
    }

    k_gather<<<7168, 256>>>(xf, rf, ent_ix, rel_ix, quals_ix, out);
}